// round 9
// baseline (speedup 1.0000x reference)
#include <cuda_runtime.h>
#include <math_constants.h>

#define PRE    1024
#define POSTN  1024
#define BATCH  32
#define NBK    64
#define WIDTH  0.03125f
#define CAP    96          // fallback gather capacity
#define CAP2   40          // staged per-bucket capacity (lambda<=24)
#define SLO    8           // staged bucket range [SLO, SHI)
#define SHI    24
#define NSTG   (SHI - SLO) // 16
#define NTH    256
#define NWARP  8
#define FULLM  0xffffffffu
#define P0B    24          // pass-0 buckets [0,24) <=> t < 0.75

// Transposed copies of delays/weights: [post][pre]
__device__ float g_dT[POSTN * PRE];
__device__ float g_wT[POSTN * PRE];

// ---------------------------------------------------------------------------
__global__ void transpose_kernel(const float* __restrict__ W,
                                 const float* __restrict__ D)
{
    __shared__ float tw[32][33];
    __shared__ float td[32][33];
    int x  = blockIdx.x * 32 + threadIdx.x;
    int y0 = blockIdx.y * 32;
#pragma unroll
    for (int j = 0; j < 32; j += 8) {
        tw[threadIdx.y + j][threadIdx.x] = W[(size_t)(y0 + threadIdx.y + j) * POSTN + x];
        td[threadIdx.y + j][threadIdx.x] = D[(size_t)(y0 + threadIdx.y + j) * POSTN + x];
    }
    __syncthreads();
    int xo  = blockIdx.y * 32 + threadIdx.x;
    int yo0 = blockIdx.x * 32;
#pragma unroll
    for (int j = 0; j < 32; j += 8) {
        g_wT[(size_t)(yo0 + threadIdx.y + j) * PRE + xo] = tw[threadIdx.x][threadIdx.y + j];
        g_dT[(size_t)(yo0 + threadIdx.y + j) * PRE + xo] = td[threadIdx.x][threadIdx.y + j];
    }
}

// ---------------------------------------------------------------------------
// Sort bT/bW[0..cnt) in shared by time (position tie-break), warp-collective.
// ---------------------------------------------------------------------------
__device__ __forceinline__ void sort_shared(float* bT, float* bW, int cnt, int lane)
{
    if (cnt <= 1) return;
    float rt[3], rw[3];
    int   rk[3];
#pragma unroll
    for (int r = 0; r < 3; r++) {
        int p = lane + 32 * r;
        bool on = (p < cnt);
        rt[r] = on ? bT[p] : CUDART_INF_F;
        rw[r] = on ? bW[p] : 0.f;
        rk[r] = 0;
    }
    __syncwarp();
    for (int s = 0; s < cnt; s++) {
        float tb = bT[s];
#pragma unroll
        for (int q = 0; q < 3; q++) {
            int myp = lane + 32 * q;
            if (myp < cnt)
                rk[q] += (tb < rt[q]) || (tb == rt[q] && s < myp);
        }
    }
    __syncwarp();
#pragma unroll
    for (int q = 0; q < 3; q++)
        if (lane + 32 * q < cnt) { bT[rk[q]] = rt[q]; bW[rk[q]] = rw[q]; }
    __syncwarp();
}

// ---------------------------------------------------------------------------
// Evaluate sorted bucket j (events bT/bW[0..cnt)) for the first crossing of
// V(t)=cumw*t-cumwt against theta. Returns true + *outres on success.
// ---------------------------------------------------------------------------
__device__ __forceinline__ bool eval_sorted(
    int j, float theta, float cw, float cwt, int cnt,
    const float* bT, const float* bW, int lane, float* outres)
{
    bool  found = false;
    float tmp = 0.f;
    for (int c0 = 0; c0 < cnt && !found; c0 += 32) {
        int  k  = c0 + lane;
        bool on = (k < cnt);
        float tk = on ? bT[k] : 0.f;
        float wk = on ? bW[k] : 0.f;
        float swi = wk, swti = wk * tk;
#pragma unroll
        for (int o = 1; o < 32; o <<= 1) {
            float u = __shfl_up_sync(FULLM, swi,  o);
            float v = __shfl_up_sync(FULLM, swti, o);
            if (lane >= o) { swi += u; swti += v; }
        }
        float CWp  = cw  + swi  - wk;         // prefix BEFORE event k
        float CWTp = cwt + swti - wk * tk;
        float V    = CWp * tk - CWTp;
        bool cross = on && (V >= theta) && (CWp > 0.f);
        unsigned cb = __ballot_sync(FULLM, cross);
        if (cb) {
            int fl = __ffs(cb) - 1;
            float cand = (theta + CWTp) / CWp;
            tmp = __shfl_sync(FULLM, cand, fl);
            found = true;
        } else {
            int lastl = min(31, cnt - 1 - c0);
            cw  += __shfl_sync(FULLM, swi,  lastl);
            cwt += __shfl_sync(FULLM, swti, lastl);
        }
    }
    if (!found) {
        float edge = (float)(j + 1) * WIDTH;
        if (cw > 0.f && cw * edge - cwt >= theta) {  // drift crossing before edge
            tmp = (theta + cwt) / cw;
            found = true;
        }
    }
    if (found) *outres = tmp;
    return found;
}

// ---------------------------------------------------------------------------
// Fallback: gather bucket-j events by full global re-sweep (L1-hot), then
// sort + eval. Scratch bT/bW must hold >= CAP floats each.
// ---------------------------------------------------------------------------
__device__ __forceinline__ bool gse_fallback(
    int j, float theta, float cw, float cwt,
    const float* __restrict__ sp, const float* __restrict__ dT,
    const float* __restrict__ wT,
    float* bT, float* bW, int lane, float* outres)
{
    int cnt = 0;
#pragma unroll
    for (int r = 0; r < 8; r++) {
        int i0 = r * 128 + lane * 4;
        float4 s4 = *reinterpret_cast<const float4*>(sp + i0);
        float4 d4 = *reinterpret_cast<const float4*>(dT + i0);
        float4 w4 = *reinterpret_cast<const float4*>(wT + i0);
        float tq[4] = { s4.x + d4.x, s4.y + d4.y, s4.z + d4.z, s4.w + d4.w };
        float wq[4] = { w4.x, w4.y, w4.z, w4.w };
#pragma unroll
        for (int q = 0; q < 4; q++) {
            int bb = (int)(tq[q] * 32.0f);
            bb = max(0, min(bb, NBK - 1));
            bool in = (bb == j);
            unsigned m = __ballot_sync(FULLM, in);
            int pos = cnt + __popc(m & ((1u << lane) - 1));
            if (in && pos < CAP) { bT[pos] = tq[q]; bW[pos] = wq[q]; }
            cnt += __popc(m);
        }
    }
    cnt = min(cnt, CAP);
    __syncwarp();
    sort_shared(bT, bW, cnt, lane);
    return eval_sorted(j, theta, cw, cwt, cnt, bT, bW, lane, outres);
}

// ---------------------------------------------------------------------------
// One WARP per (batch, post) problem. No block-wide barriers.
// ---------------------------------------------------------------------------
__global__ __launch_bounds__(NTH, 4)
void equaltime_kernel(const float* __restrict__ spikes,
                      const float* __restrict__ thresholds,
                      float* __restrict__ out)
{
    __shared__ float sW[NWARP][NBK], sWT[NWARP][NBK], sWp[NWARP][NBK];
    __shared__ int   sCnt[NWARP][NSTG];
    __shared__ float sStg[NWARP][2 * NSTG * CAP2];  // [T rows | W rows]

    const int lane = threadIdx.x & 31;
    const int wid  = threadIdx.x >> 5;
    const int pid  = blockIdx.x * NWARP + wid;
    const int post = pid >> 5;
    const int b    = pid & 31;

    const float theta = thresholds[post];
    const float* dT = g_dT + (size_t)post * PRE;
    const float* wT = g_wT + (size_t)post * PRE;
    const float* sp = spikes + (size_t)b * PRE;
    float* mW  = sW[wid];
    float* mWT = sWT[wid];
    float* mWp = sWp[wid];
    int*   mCnt = sCnt[wid];
    float* stT = sStg[wid];                 // NSTG*CAP2 floats
    float* stW = sStg[wid] + NSTG * CAP2;   // NSTG*CAP2 floats

    if (lane < P0B) { mW[lane] = 0.f; mWT[lane] = 0.f; mWp[lane] = 0.f; }
    if (lane < NSTG) mCnt[lane] = 0;
    __syncwarp();

    // ---- pass-0 sweep: bin sums for buckets [0,24), stage events [8,24) ----
#pragma unroll
    for (int r = 0; r < 8; r++) {
        int i0 = r * 128 + lane * 4;
        float4 s4 = *reinterpret_cast<const float4*>(sp + i0);
        float4 d4 = *reinterpret_cast<const float4*>(dT + i0);
        float4 w4 = *reinterpret_cast<const float4*>(wT + i0);
        float tq[4] = { s4.x + d4.x, s4.y + d4.y, s4.z + d4.z, s4.w + d4.w };
        float wq[4] = { w4.x, w4.y, w4.z, w4.w };
#pragma unroll
        for (int q = 0; q < 4; q++) {
            int bb = (int)(tq[q] * 32.0f);
            bb = max(0, min(bb, NBK - 1));
            if (bb < P0B) {
                atomicAdd(&mW[bb],  wq[q]);
                atomicAdd(&mWT[bb], wq[q] * tq[q]);
                atomicAdd(&mWp[bb], fmaxf(wq[q], 0.f));
            }
            // staged scatter with match-aggregated cursor (deterministic)
            bool instg = (bb >= SLO) && (bb < SHI);
            int key = instg ? bb : (64 + lane);
            unsigned mm = __match_any_sync(FULLM, key);
            if (instg) {
                int idx = bb - SLO;
                int leader = __ffs(mm) - 1;
                int base = 0;
                if (lane == leader) base = atomicAdd(&mCnt[idx], __popc(mm));
                base = __shfl_sync(mm, base, leader);
                int pos = base + __popc(mm & ((1u << lane) - 1));
                if (pos < CAP2) {
                    stT[idx * CAP2 + pos] = tq[q];
                    stW[idx * CAP2 + pos] = wq[q];
                }
            }
        }
    }
    __syncwarp();

    // ---- scan pass-0 bins, flag candidate buckets ----
    float wj  = (lane < P0B) ? mW[lane]  : 0.f;
    float wtj = (lane < P0B) ? mWT[lane] : 0.f;
    float a = wj, c = wtj;
#pragma unroll
    for (int o = 1; o < 32; o <<= 1) {
        float u = __shfl_up_sync(FULLM, a, o);
        float v = __shfl_up_sync(FULLM, c, o);
        if (lane >= o) { a += u; c += v; }
    }
    float e = a - wj, f = c - wtj;                 // exclusive prefixes
    float V = e * (lane * WIDTH) - f;
    float wp = (lane < P0B) ? mWp[lane] : 0.f;
    bool fl = (lane < P0B) && (V + fmaxf(e + wp, 0.f) * WIDTH >= theta);
    unsigned fm = __ballot_sync(FULLM, fl);

    float res  = CUDART_INF_F;
    bool  done = false;
    bool  dirty = false;   // fallback scratch overwrites staging
    while (fm) {
        int j = __ffs(fm) - 1;
        fm &= fm - 1;
        float cw0  = __shfl_sync(FULLM, e, j);
        float cwt0 = __shfl_sync(FULLM, f, j);
        bool staged = (!dirty) && (j >= SLO) && (j < SHI);
        if (staged) {
            int idx = j - SLO;
            int n = mCnt[idx];
            if (n <= CAP2) {
                float* bT = stT + idx * CAP2;
                float* bW = stW + idx * CAP2;
                sort_shared(bT, bW, n, lane);
                if (eval_sorted(j, theta, cw0, cwt0, n, bT, bW, lane, &res)) {
                    done = true; break;
                }
                continue;
            }
        }
        dirty = true;
        if (gse_fallback(j, theta, cw0, cwt0, sp, dT, wT,
                         stT, stW, lane, &res)) { done = true; break; }
    }

    // ---- pass 1 (crossing at t >= 0.75; probability ~1e-14, exact path) ----
    if (!done) {
        for (int jj = P0B + lane; jj < NBK; jj += 32) {
            mW[jj] = 0.f; mWT[jj] = 0.f; mWp[jj] = 0.f;
        }
        __syncwarp();
#pragma unroll
        for (int r = 0; r < 8; r++) {
            int i0 = r * 128 + lane * 4;
            float4 s4 = *reinterpret_cast<const float4*>(sp + i0);
            float4 d4 = *reinterpret_cast<const float4*>(dT + i0);
            float4 w4 = *reinterpret_cast<const float4*>(wT + i0);
            float tq[4] = { s4.x + d4.x, s4.y + d4.y, s4.z + d4.z, s4.w + d4.w };
            float wq[4] = { w4.x, w4.y, w4.z, w4.w };
#pragma unroll
            for (int q = 0; q < 4; q++) {
                int bb = (int)(tq[q] * 32.0f);
                bb = max(0, min(bb, NBK - 1));
                if (bb >= P0B) {
                    atomicAdd(&mW[bb],  wq[q]);
                    atomicAdd(&mWT[bb], wq[q] * tq[q]);
                    atomicAdd(&mWp[bb], fmaxf(wq[q], 0.f));
                }
            }
        }
        __syncwarp();

        float w0  = mW[lane],  w1  = mW[lane + 32];
        float wt0 = mWT[lane], wt1 = mWT[lane + 32];
        float a0 = w0, a1 = w1, b0 = wt0, b1 = wt1;
#pragma unroll
        for (int o = 1; o < 32; o <<= 1) {
            float u0 = __shfl_up_sync(FULLM, a0, o);
            float u1 = __shfl_up_sync(FULLM, a1, o);
            float v0 = __shfl_up_sync(FULLM, b0, o);
            float v1 = __shfl_up_sync(FULLM, b1, o);
            if (lane >= o) { a0 += u0; a1 += u1; b0 += v0; b1 += v1; }
        }
        float T0  = __shfl_sync(FULLM, a0, 31);
        float TW0 = __shfl_sync(FULLM, b0, 31);
        a1 += T0; b1 += TW0;
        float e0 = a0 - w0,  e1 = a1 - w1;
        float f0 = b0 - wt0, f1 = b1 - wt1;
        float cwTot  = __shfl_sync(FULLM, a1, 31);
        float cwtTot = __shfl_sync(FULLM, b1, 31);
        float V0 = e0 * (lane * WIDTH) - f0;
        float V1 = e1 * ((lane + 32) * WIDTH) - f1;
        bool fl0 = (lane >= P0B) &&
                   (V0 + fmaxf(e0 + mWp[lane], 0.f) * WIDTH >= theta);
        bool fl1 = (V1 + fmaxf(e1 + mWp[lane + 32], 0.f) * WIDTH >= theta);
        unsigned m0 = __ballot_sync(FULLM, fl0);
        unsigned m1 = __ballot_sync(FULLM, fl1);

        while (m0) {
            int j = __ffs(m0) - 1;
            m0 &= m0 - 1;
            float cw0  = __shfl_sync(FULLM, e0, j);
            float cwt0 = __shfl_sync(FULLM, f0, j);
            if (gse_fallback(j, theta, cw0, cwt0, sp, dT, wT,
                             stT, stW, lane, &res)) { done = true; break; }
        }
        while (!done && m1) {
            int jl = __ffs(m1) - 1;
            m1 &= m1 - 1;
            float cw0  = __shfl_sync(FULLM, e1, jl);
            float cwt0 = __shfl_sync(FULLM, f1, jl);
            if (gse_fallback(jl + 32, theta, cw0, cwt0, sp, dT, wT,
                             stT, stW, lane, &res)) { done = true; break; }
        }
        if (!done)
            res = (cwTot > 0.f) ? (theta + cwtTot) / cwTot : CUDART_INF_F;
    }

    if (lane == 0) out[(size_t)b * POSTN + post] = res;
}

// ---------------------------------------------------------------------------
extern "C" void kernel_launch(void* const* d_in, const int* in_sizes, int n_in,
                              void* d_out, int out_size)
{
    const float* spikes  = (const float*)d_in[0];  // [32, 1024]
    const float* weights = (const float*)d_in[1];  // [1024, 1024]
    const float* delays  = (const float*)d_in[2];  // [1024, 1024]
    const float* thr     = (const float*)d_in[3];  // [1024]
    float* out = (float*)d_out;                    // [32, 1024]

    dim3 tb(32, 8);
    dim3 tg(POSTN / 32, PRE / 32);
    transpose_kernel<<<tg, tb>>>(weights, delays);

    equaltime_kernel<<<(BATCH * POSTN) / NWARP, NTH>>>(spikes, thr, out);
}

// round 10
// speedup vs baseline: 1.8345x; 1.8345x over previous
#include <cuda_runtime.h>
#include <math_constants.h>

#define PRE    1024
#define POSTN  1024
#define BATCH  32
#define NBK    64
#define WIDTH  0.03125f
#define CAP    96          // gather capacity (merged-run or single bucket)
#define NTH    256
#define NWARP  8
#define FULLM  0xffffffffu
#define P0B    21          // pass-0 buckets [0,21) <=> t < 0.65625
#define MRUN   3           // max buckets merged into one gather

// Transposed copies of delays/weights: [post][pre]
__device__ float g_dT[POSTN * PRE];
__device__ float g_wT[POSTN * PRE];

// ---------------------------------------------------------------------------
__global__ void transpose_kernel(const float* __restrict__ W,
                                 const float* __restrict__ D)
{
    __shared__ float tw[32][33];
    __shared__ float td[32][33];
    int x  = blockIdx.x * 32 + threadIdx.x;
    int y0 = blockIdx.y * 32;
#pragma unroll
    for (int j = 0; j < 32; j += 8) {
        tw[threadIdx.y + j][threadIdx.x] = W[(size_t)(y0 + threadIdx.y + j) * POSTN + x];
        td[threadIdx.y + j][threadIdx.x] = D[(size_t)(y0 + threadIdx.y + j) * POSTN + x];
    }
    __syncthreads();
    int xo  = blockIdx.y * 32 + threadIdx.x;
    int yo0 = blockIdx.x * 32;
#pragma unroll
    for (int j = 0; j < 32; j += 8) {
        g_wT[(size_t)(yo0 + threadIdx.y + j) * PRE + xo] = tw[threadIdx.x][threadIdx.y + j];
        g_dT[(size_t)(yo0 + threadIdx.y + j) * PRE + xo] = td[threadIdx.x][threadIdx.y + j];
    }
}

// ---------------------------------------------------------------------------
// Gather all events with bucket in [j0, j1] into bT/bW (ballot-compacted,
// deterministic order). Returns TRUE total count (stores capped at CAP).
// ---------------------------------------------------------------------------
__device__ __forceinline__ int gather_range(
    int j0, int j1,
    const float* __restrict__ sp, const float* __restrict__ dT,
    const float* __restrict__ wT,
    float* bT, float* bW, int lane)
{
    int cnt = 0;
#pragma unroll
    for (int r = 0; r < 8; r++) {
        int i0 = r * 128 + lane * 4;
        float4 s4 = *reinterpret_cast<const float4*>(sp + i0);
        float4 d4 = *reinterpret_cast<const float4*>(dT + i0);
        float4 w4 = *reinterpret_cast<const float4*>(wT + i0);
        float tq[4] = { s4.x + d4.x, s4.y + d4.y, s4.z + d4.z, s4.w + d4.w };
        float wq[4] = { w4.x, w4.y, w4.z, w4.w };
#pragma unroll
        for (int q = 0; q < 4; q++) {
            int bb = (int)(tq[q] * 32.0f);
            bb = max(0, min(bb, NBK - 1));
            bool in = (bb >= j0) && (bb <= j1);
            unsigned m = __ballot_sync(FULLM, in);
            int pos = cnt + __popc(m & ((1u << lane) - 1));
            if (in && pos < CAP) { bT[pos] = tq[q]; bW[pos] = wq[q]; }
            cnt += __popc(m);
        }
    }
    __syncwarp();
    return cnt;
}

// ---------------------------------------------------------------------------
// Sort bT/bW[0..cnt) in shared by time (position tie-break), warp-collective.
// ---------------------------------------------------------------------------
__device__ __forceinline__ void sort_shared(float* bT, float* bW, int cnt, int lane)
{
    if (cnt <= 1) return;
    float rt[3], rw[3];
    int   rk[3];
#pragma unroll
    for (int r = 0; r < 3; r++) {
        int p = lane + 32 * r;
        bool on = (p < cnt);
        rt[r] = on ? bT[p] : CUDART_INF_F;
        rw[r] = on ? bW[p] : 0.f;
        rk[r] = 0;
    }
    __syncwarp();
    for (int s = 0; s < cnt; s++) {
        float tb = bT[s];
#pragma unroll
        for (int q = 0; q < 3; q++) {
            int myp = lane + 32 * q;
            if (myp < cnt)
                rk[q] += (tb < rt[q]) || (tb == rt[q] && s < myp);
        }
    }
    __syncwarp();
#pragma unroll
    for (int q = 0; q < 3; q++)
        if (lane + 32 * q < cnt) { bT[rk[q]] = rt[q]; bW[rk[q]] = rw[q]; }
    __syncwarp();
}

// ---------------------------------------------------------------------------
// Evaluate sorted events bT/bW[0..cnt) (covering buckets up to jEdge) for the
// first crossing of V(t)=cumw*t-cumwt against theta. cw/cwt = prefix at the
// range start. Drift crossing checked up to edge (jEdge+1)*WIDTH.
// ---------------------------------------------------------------------------
__device__ __forceinline__ bool eval_sorted(
    int jEdge, float theta, float cw, float cwt, int cnt,
    const float* bT, const float* bW, int lane, float* outres)
{
    bool  found = false;
    float tmp = 0.f;
    for (int c0 = 0; c0 < cnt && !found; c0 += 32) {
        int  k  = c0 + lane;
        bool on = (k < cnt);
        float tk = on ? bT[k] : 0.f;
        float wk = on ? bW[k] : 0.f;
        float swi = wk, swti = wk * tk;
#pragma unroll
        for (int o = 1; o < 32; o <<= 1) {
            float u = __shfl_up_sync(FULLM, swi,  o);
            float v = __shfl_up_sync(FULLM, swti, o);
            if (lane >= o) { swi += u; swti += v; }
        }
        float CWp  = cw  + swi  - wk;         // prefix BEFORE event k
        float CWTp = cwt + swti - wk * tk;
        float V    = CWp * tk - CWTp;
        bool cross = on && (V >= theta) && (CWp > 0.f);
        unsigned cb = __ballot_sync(FULLM, cross);
        if (cb) {
            int fl = __ffs(cb) - 1;
            float cand = (theta + CWTp) / CWp;
            tmp = __shfl_sync(FULLM, cand, fl);
            found = true;
        } else {
            int lastl = min(31, cnt - 1 - c0);
            cw  += __shfl_sync(FULLM, swi,  lastl);
            cwt += __shfl_sync(FULLM, swti, lastl);
        }
    }
    if (!found) {
        float edge = (float)(jEdge + 1) * WIDTH;
        if (cw > 0.f && cw * edge - cwt >= theta) {  // drift crossing before edge
            tmp = (theta + cwt) / cw;
            found = true;
        }
    }
    if (found) *outres = tmp;
    return found;
}

// ---------------------------------------------------------------------------
// One WARP per (batch, post) problem. No block-wide barriers.
// ---------------------------------------------------------------------------
__global__ __launch_bounds__(NTH)
void equaltime_kernel(const float* __restrict__ spikes,
                      const float* __restrict__ thresholds,
                      float* __restrict__ out)
{
    __shared__ float sW[NWARP][NBK], sWT[NWARP][NBK], sWp[NWARP][NBK];
    __shared__ float sbT[NWARP][CAP], sbW[NWARP][CAP];

    const int lane = threadIdx.x & 31;
    const int wid  = threadIdx.x >> 5;
    const int pid  = blockIdx.x * NWARP + wid;
    const int post = pid >> 5;
    const int b    = pid & 31;

    const float theta = thresholds[post];
    const float* dT = g_dT + (size_t)post * PRE;
    const float* wT = g_wT + (size_t)post * PRE;
    const float* sp = spikes + (size_t)b * PRE;
    float* mW  = sW[wid];
    float* mWT = sWT[wid];
    float* mWp = sWp[wid];
    float* bT  = sbT[wid];
    float* bW  = sbW[wid];

    if (lane < P0B) { mW[lane] = 0.f; mWT[lane] = 0.f; mWp[lane] = 0.f; }
    __syncwarp();

    // ---- pass-0 sweep: bin sums for buckets [0,P0B) ----
#pragma unroll
    for (int r = 0; r < 8; r++) {
        int i0 = r * 128 + lane * 4;
        float4 s4 = *reinterpret_cast<const float4*>(sp + i0);
        float4 d4 = *reinterpret_cast<const float4*>(dT + i0);
        float4 w4 = *reinterpret_cast<const float4*>(wT + i0);
        float tq[4] = { s4.x + d4.x, s4.y + d4.y, s4.z + d4.z, s4.w + d4.w };
        float wq[4] = { w4.x, w4.y, w4.z, w4.w };
#pragma unroll
        for (int q = 0; q < 4; q++) {
            int bb = (int)(tq[q] * 32.0f);
            bb = max(0, min(bb, NBK - 1));
            if (bb < P0B) {
                atomicAdd(&mW[bb],  wq[q]);
                atomicAdd(&mWT[bb], wq[q] * tq[q]);
                if (wq[q] > 0.f) atomicAdd(&mWp[bb], wq[q]);
            }
        }
    }
    __syncwarp();

    // ---- scan pass-0 bins, flag candidate buckets ----
    float wj  = (lane < P0B) ? mW[lane]  : 0.f;
    float wtj = (lane < P0B) ? mWT[lane] : 0.f;
    float a = wj, c = wtj;
#pragma unroll
    for (int o = 1; o < 32; o <<= 1) {
        float u = __shfl_up_sync(FULLM, a, o);
        float v = __shfl_up_sync(FULLM, c, o);
        if (lane >= o) { a += u; c += v; }
    }
    float e = a - wj, f = c - wtj;                 // exclusive prefixes
    float V = e * (lane * WIDTH) - f;
    float wp = (lane < P0B) ? mWp[lane] : 0.f;
    bool fl = (lane < P0B) && (V + fmaxf(e + wp, 0.f) * WIDTH >= theta);
    unsigned fm = __ballot_sync(FULLM, fl);

    float res  = CUDART_INF_F;
    bool  done = false;

    // ---- merged-run candidate loop ----
    while (!done && fm) {
        int jf = __ffs(fm) - 1;
        unsigned sh = fm >> jf;                    // bit0 == 1
        int run  = __ffs(~sh) - 1;                 // contiguous flagged length
        int nrun = min(run, MRUN);
        int jl   = jf + nrun - 1;

        int cnt = gather_range(jf, jl, sp, dT, wT, bT, bW, lane);
        if (cnt > CAP) {                            // ~1e-6: retry single bucket
            nrun = 1; jl = jf;
            cnt = gather_range(jf, jf, sp, dT, wT, bT, bW, lane);
            cnt = min(cnt, CAP);
        }
        sort_shared(bT, bW, cnt, lane);
        float cw0  = __shfl_sync(FULLM, e, jf);
        float cwt0 = __shfl_sync(FULLM, f, jf);
        if (eval_sorted(jl, theta, cw0, cwt0, cnt, bT, bW, lane, &res)) {
            done = true; break;
        }
        fm &= ~(((1u << nrun) - 1) << jf);
    }

    // ---- pass 1 (crossing at t >= 0.65625; ~8e-4 of problems, exact path) ----
    if (!done) {
        for (int jj = P0B + lane; jj < NBK; jj += 32) {
            mW[jj] = 0.f; mWT[jj] = 0.f; mWp[jj] = 0.f;
        }
        __syncwarp();
#pragma unroll
        for (int r = 0; r < 8; r++) {
            int i0 = r * 128 + lane * 4;
            float4 s4 = *reinterpret_cast<const float4*>(sp + i0);
            float4 d4 = *reinterpret_cast<const float4*>(dT + i0);
            float4 w4 = *reinterpret_cast<const float4*>(wT + i0);
            float tq[4] = { s4.x + d4.x, s4.y + d4.y, s4.z + d4.z, s4.w + d4.w };
            float wq[4] = { w4.x, w4.y, w4.z, w4.w };
#pragma unroll
            for (int q = 0; q < 4; q++) {
                int bb = (int)(tq[q] * 32.0f);
                bb = max(0, min(bb, NBK - 1));
                if (bb >= P0B) {
                    atomicAdd(&mW[bb],  wq[q]);
                    atomicAdd(&mWT[bb], wq[q] * tq[q]);
                    if (wq[q] > 0.f) atomicAdd(&mWp[bb], wq[q]);
                }
            }
        }
        __syncwarp();

        float w0  = mW[lane],  w1  = mW[lane + 32];
        float wt0 = mWT[lane], wt1 = mWT[lane + 32];
        float a0 = w0, a1 = w1, b0 = wt0, b1 = wt1;
#pragma unroll
        for (int o = 1; o < 32; o <<= 1) {
            float u0 = __shfl_up_sync(FULLM, a0, o);
            float u1 = __shfl_up_sync(FULLM, a1, o);
            float v0 = __shfl_up_sync(FULLM, b0, o);
            float v1 = __shfl_up_sync(FULLM, b1, o);
            if (lane >= o) { a0 += u0; a1 += u1; b0 += v0; b1 += v1; }
        }
        float T0  = __shfl_sync(FULLM, a0, 31);
        float TW0 = __shfl_sync(FULLM, b0, 31);
        a1 += T0; b1 += TW0;
        float e0 = a0 - w0,  e1 = a1 - w1;
        float f0 = b0 - wt0, f1 = b1 - wt1;
        float cwTot  = __shfl_sync(FULLM, a1, 31);
        float cwtTot = __shfl_sync(FULLM, b1, 31);
        float V0 = e0 * (lane * WIDTH) - f0;
        float V1 = e1 * ((lane + 32) * WIDTH) - f1;
        bool fl0 = (lane >= P0B) &&
                   (V0 + fmaxf(e0 + mWp[lane], 0.f) * WIDTH >= theta);
        bool fl1 = (V1 + fmaxf(e1 + mWp[lane + 32], 0.f) * WIDTH >= theta);
        unsigned m0 = __ballot_sync(FULLM, fl0);
        unsigned m1 = __ballot_sync(FULLM, fl1);

        while (!done && m0) {
            int j = __ffs(m0) - 1;
            m0 &= m0 - 1;
            float cw0  = __shfl_sync(FULLM, e0, j);
            float cwt0 = __shfl_sync(FULLM, f0, j);
            int cnt = min(gather_range(j, j, sp, dT, wT, bT, bW, lane), CAP);
            sort_shared(bT, bW, cnt, lane);
            if (eval_sorted(j, theta, cw0, cwt0, cnt, bT, bW, lane, &res))
                done = true;
        }
        while (!done && m1) {
            int jl2 = __ffs(m1) - 1;
            m1 &= m1 - 1;
            float cw0  = __shfl_sync(FULLM, e1, jl2);
            float cwt0 = __shfl_sync(FULLM, f1, jl2);
            int j = jl2 + 32;
            int cnt = min(gather_range(j, j, sp, dT, wT, bT, bW, lane), CAP);
            sort_shared(bT, bW, cnt, lane);
            if (eval_sorted(j, theta, cw0, cwt0, cnt, bT, bW, lane, &res))
                done = true;
        }
        if (!done)
            res = (cwTot > 0.f) ? (theta + cwtTot) / cwTot : CUDART_INF_F;
    }

    if (lane == 0) out[(size_t)b * POSTN + post] = res;
}

// ---------------------------------------------------------------------------
extern "C" void kernel_launch(void* const* d_in, const int* in_sizes, int n_in,
                              void* d_out, int out_size)
{
    const float* spikes  = (const float*)d_in[0];  // [32, 1024]
    const float* weights = (const float*)d_in[1];  // [1024, 1024]
    const float* delays  = (const float*)d_in[2];  // [1024, 1024]
    const float* thr     = (const float*)d_in[3];  // [1024]
    float* out = (float*)d_out;                    // [32, 1024]

    dim3 tb(32, 8);
    dim3 tg(POSTN / 32, PRE / 32);
    transpose_kernel<<<tg, tb>>>(weights, delays);

    equaltime_kernel<<<(BATCH * POSTN) / NWARP, NTH>>>(spikes, thr, out);
}

// round 11
// speedup vs baseline: 1.8399x; 1.0029x over previous
#include <cuda_runtime.h>
#include <math_constants.h>

#define PRE    1024
#define POSTN  1024
#define BATCH  32
#define NBK    64
#define WIDTH  0.03125f
#define CAP    96          // gather capacity (merged-run or single bucket)
#define NTH    256
#define NWARP  8
#define FULLM  0xffffffffu
#define P0B    21          // pass-0 buckets [0,21) <=> t < 0.65625
#define MRUN   4           // max buckets merged into one gather

// Transposed copies of delays/weights: [post][pre]
__device__ float g_dT[POSTN * PRE];
__device__ float g_wT[POSTN * PRE];

// ---------------------------------------------------------------------------
__global__ void transpose_kernel(const float* __restrict__ W,
                                 const float* __restrict__ D)
{
    __shared__ float tw[32][33];
    __shared__ float td[32][33];
    int x  = blockIdx.x * 32 + threadIdx.x;
    int y0 = blockIdx.y * 32;
#pragma unroll
    for (int j = 0; j < 32; j += 8) {
        tw[threadIdx.y + j][threadIdx.x] = W[(size_t)(y0 + threadIdx.y + j) * POSTN + x];
        td[threadIdx.y + j][threadIdx.x] = D[(size_t)(y0 + threadIdx.y + j) * POSTN + x];
    }
    __syncthreads();
    int xo  = blockIdx.y * 32 + threadIdx.x;
    int yo0 = blockIdx.x * 32;
#pragma unroll
    for (int j = 0; j < 32; j += 8) {
        g_wT[(size_t)(yo0 + threadIdx.y + j) * PRE + xo] = tw[threadIdx.x][threadIdx.y + j];
        g_dT[(size_t)(yo0 + threadIdx.y + j) * PRE + xo] = td[threadIdx.x][threadIdx.y + j];
    }
}

// ---------------------------------------------------------------------------
// Gather (t, original-index) of all events with bucket in [j0, j1].
// Loads only spikes+delays (membership needs just t). Returns TRUE count.
// ---------------------------------------------------------------------------
__device__ __forceinline__ int gather_range(
    int j0, int j1,
    const float* __restrict__ sp, const float* __restrict__ dT,
    float* bT, int* bI, int lane)
{
    int cnt = 0;
#pragma unroll
    for (int r = 0; r < 8; r++) {
        int i0 = r * 128 + lane * 4;
        float4 s4 = *reinterpret_cast<const float4*>(sp + i0);
        float4 d4 = *reinterpret_cast<const float4*>(dT + i0);
        float tq[4] = { s4.x + d4.x, s4.y + d4.y, s4.z + d4.z, s4.w + d4.w };
#pragma unroll
        for (int q = 0; q < 4; q++) {
            int bb = (int)(tq[q] * 32.0f);
            bb = max(0, min(bb, NBK - 1));
            bool in = (bb >= j0) && (bb <= j1);
            unsigned m = __ballot_sync(FULLM, in);
            int pos = cnt + __popc(m & ((1u << lane) - 1));
            if (in && pos < CAP) { bT[pos] = tq[q]; bI[pos] = i0 + q; }
            cnt += __popc(m);
        }
    }
    __syncwarp();
    return cnt;
}

// ---------------------------------------------------------------------------
// Sort (bT, bI)[0..cnt) by time (position tie-break), warp-collective.
// ---------------------------------------------------------------------------
__device__ __forceinline__ void sort_shared(float* bT, int* bI, int cnt, int lane)
{
    if (cnt <= 1) return;
    float rt[3];
    int   ri[3], rk[3];
#pragma unroll
    for (int r = 0; r < 3; r++) {
        int p = lane + 32 * r;
        bool on = (p < cnt);
        rt[r] = on ? bT[p] : CUDART_INF_F;
        ri[r] = on ? bI[p] : 0;
        rk[r] = 0;
    }
    __syncwarp();
    for (int s = 0; s < cnt; s++) {
        float tb = bT[s];
#pragma unroll
        for (int q = 0; q < 3; q++) {
            int myp = lane + 32 * q;
            if (myp < cnt)
                rk[q] += (tb < rt[q]) || (tb == rt[q] && s < myp);
        }
    }
    __syncwarp();
#pragma unroll
    for (int q = 0; q < 3; q++)
        if (lane + 32 * q < cnt) { bT[rk[q]] = rt[q]; bI[rk[q]] = ri[q]; }
    __syncwarp();
}

// ---------------------------------------------------------------------------
// Evaluate sorted events (times bT, weights via wT[bI]) for the first
// crossing of V(t)=cumw*t-cumwt against theta. cw/cwt = prefix at range
// start. Drift crossing checked up to edge (jEdge+1)*WIDTH.
// ---------------------------------------------------------------------------
__device__ __forceinline__ bool eval_sorted(
    int jEdge, float theta, float cw, float cwt, int cnt,
    const float* bT, const int* bI, const float* __restrict__ wT,
    int lane, float* outres)
{
    bool  found = false;
    float tmp = 0.f;
    for (int c0 = 0; c0 < cnt && !found; c0 += 32) {
        int  k  = c0 + lane;
        bool on = (k < cnt);
        float tk = on ? bT[k] : 0.f;
        float wk = on ? wT[bI[k]] : 0.f;
        float swi = wk, swti = wk * tk;
#pragma unroll
        for (int o = 1; o < 32; o <<= 1) {
            float u = __shfl_up_sync(FULLM, swi,  o);
            float v = __shfl_up_sync(FULLM, swti, o);
            if (lane >= o) { swi += u; swti += v; }
        }
        float CWp  = cw  + swi  - wk;         // prefix BEFORE event k
        float CWTp = cwt + swti - wk * tk;
        float V    = CWp * tk - CWTp;
        bool cross = on && (V >= theta) && (CWp > 0.f);
        unsigned cb = __ballot_sync(FULLM, cross);
        if (cb) {
            int fl = __ffs(cb) - 1;
            float cand = (theta + CWTp) / CWp;
            tmp = __shfl_sync(FULLM, cand, fl);
            found = true;
        } else {
            int lastl = min(31, cnt - 1 - c0);
            cw  += __shfl_sync(FULLM, swi,  lastl);
            cwt += __shfl_sync(FULLM, swti, lastl);
        }
    }
    if (!found) {
        float edge = (float)(jEdge + 1) * WIDTH;
        if (cw > 0.f && cw * edge - cwt >= theta) {  // drift crossing before edge
            tmp = (theta + cwt) / cw;
            found = true;
        }
    }
    if (found) *outres = tmp;
    return found;
}

// ---------------------------------------------------------------------------
// One WARP per (batch, post) problem. No block-wide barriers.
// ---------------------------------------------------------------------------
__global__ __launch_bounds__(NTH, 4)
void equaltime_kernel(const float* __restrict__ spikes,
                      const float* __restrict__ thresholds,
                      float* __restrict__ out)
{
    __shared__ float sW[NWARP][NBK], sWT[NWARP][NBK], sWp[NWARP][NBK];
    __shared__ float sbT[NWARP][CAP];
    __shared__ int   sbI[NWARP][CAP];

    const int lane = threadIdx.x & 31;
    const int wid  = threadIdx.x >> 5;
    const int pid  = blockIdx.x * NWARP + wid;
    const int post = pid >> 5;
    const int b    = pid & 31;

    const float theta = thresholds[post];
    const float* dT = g_dT + (size_t)post * PRE;
    const float* wT = g_wT + (size_t)post * PRE;
    const float* sp = spikes + (size_t)b * PRE;
    float* mW  = sW[wid];
    float* mWT = sWT[wid];
    float* mWp = sWp[wid];
    float* bT  = sbT[wid];
    int*   bI  = sbI[wid];

    if (lane < P0B) { mW[lane] = 0.f; mWT[lane] = 0.f; mWp[lane] = 0.f; }
    __syncwarp();

    // ---- pass-0 sweep: bin sums for buckets [0,P0B) ----
#pragma unroll
    for (int r = 0; r < 8; r++) {
        int i0 = r * 128 + lane * 4;
        float4 s4 = *reinterpret_cast<const float4*>(sp + i0);
        float4 d4 = *reinterpret_cast<const float4*>(dT + i0);
        float4 w4 = *reinterpret_cast<const float4*>(wT + i0);
        float tq[4] = { s4.x + d4.x, s4.y + d4.y, s4.z + d4.z, s4.w + d4.w };
        float wq[4] = { w4.x, w4.y, w4.z, w4.w };
#pragma unroll
        for (int q = 0; q < 4; q++) {
            int bb = (int)(tq[q] * 32.0f);
            bb = max(0, min(bb, NBK - 1));
            if (bb < P0B) {
                atomicAdd(&mW[bb],  wq[q]);
                atomicAdd(&mWT[bb], wq[q] * tq[q]);
                if (wq[q] > 0.f) atomicAdd(&mWp[bb], wq[q]);
            }
        }
    }
    __syncwarp();

    // ---- scan pass-0 bins, flag candidate buckets ----
    float wj  = (lane < P0B) ? mW[lane]  : 0.f;
    float wtj = (lane < P0B) ? mWT[lane] : 0.f;
    float a = wj, c = wtj;
#pragma unroll
    for (int o = 1; o < 32; o <<= 1) {
        float u = __shfl_up_sync(FULLM, a, o);
        float v = __shfl_up_sync(FULLM, c, o);
        if (lane >= o) { a += u; c += v; }
    }
    float e = a - wj, f = c - wtj;                 // exclusive prefixes
    float V = e * (lane * WIDTH) - f;
    float wp = (lane < P0B) ? mWp[lane] : 0.f;
    bool fl = (lane < P0B) && (V + fmaxf(e + wp, 0.f) * WIDTH >= theta);
    unsigned fm = __ballot_sync(FULLM, fl);

    float res  = CUDART_INF_F;
    bool  done = false;

    // ---- merged-run candidate loop ----
    while (!done && fm) {
        int jf = __ffs(fm) - 1;
        unsigned sh = fm >> jf;                    // bit0 == 1
        int run  = __ffs(~sh) - 1;                 // contiguous flagged length
        int nrun = min(run, MRUN);
        int jl   = jf + nrun - 1;

        int cnt = gather_range(jf, jl, sp, dT, bT, bI, lane);
        if (cnt > CAP) {                            // rare: retry single bucket
            nrun = 1; jl = jf;
            cnt = gather_range(jf, jf, sp, dT, bT, bI, lane);
            cnt = min(cnt, CAP);
        }
        sort_shared(bT, bI, cnt, lane);
        float cw0  = __shfl_sync(FULLM, e, jf);
        float cwt0 = __shfl_sync(FULLM, f, jf);
        if (eval_sorted(jl, theta, cw0, cwt0, cnt, bT, bI, wT, lane, &res)) {
            done = true; break;
        }
        fm &= ~(((1u << nrun) - 1) << jf);
    }

    // ---- pass 1 (crossing at t >= 0.65625; ~8e-4 of problems, exact path) ----
    if (!done) {
        for (int jj = P0B + lane; jj < NBK; jj += 32) {
            mW[jj] = 0.f; mWT[jj] = 0.f; mWp[jj] = 0.f;
        }
        __syncwarp();
#pragma unroll
        for (int r = 0; r < 8; r++) {
            int i0 = r * 128 + lane * 4;
            float4 s4 = *reinterpret_cast<const float4*>(sp + i0);
            float4 d4 = *reinterpret_cast<const float4*>(dT + i0);
            float4 w4 = *reinterpret_cast<const float4*>(wT + i0);
            float tq[4] = { s4.x + d4.x, s4.y + d4.y, s4.z + d4.z, s4.w + d4.w };
            float wq[4] = { w4.x, w4.y, w4.z, w4.w };
#pragma unroll
            for (int q = 0; q < 4; q++) {
                int bb = (int)(tq[q] * 32.0f);
                bb = max(0, min(bb, NBK - 1));
                if (bb >= P0B) {
                    atomicAdd(&mW[bb],  wq[q]);
                    atomicAdd(&mWT[bb], wq[q] * tq[q]);
                    if (wq[q] > 0.f) atomicAdd(&mWp[bb], wq[q]);
                }
            }
        }
        __syncwarp();

        float w0  = mW[lane],  w1  = mW[lane + 32];
        float wt0 = mWT[lane], wt1 = mWT[lane + 32];
        float a0 = w0, a1 = w1, b0 = wt0, b1 = wt1;
#pragma unroll
        for (int o = 1; o < 32; o <<= 1) {
            float u0 = __shfl_up_sync(FULLM, a0, o);
            float u1 = __shfl_up_sync(FULLM, a1, o);
            float v0 = __shfl_up_sync(FULLM, b0, o);
            float v1 = __shfl_up_sync(FULLM, b1, o);
            if (lane >= o) { a0 += u0; a1 += u1; b0 += v0; b1 += v1; }
        }
        float T0  = __shfl_sync(FULLM, a0, 31);
        float TW0 = __shfl_sync(FULLM, b0, 31);
        a1 += T0; b1 += TW0;
        float e0 = a0 - w0,  e1 = a1 - w1;
        float f0 = b0 - wt0, f1 = b1 - wt1;
        float cwTot  = __shfl_sync(FULLM, a1, 31);
        float cwtTot = __shfl_sync(FULLM, b1, 31);
        float V0 = e0 * (lane * WIDTH) - f0;
        float V1 = e1 * ((lane + 32) * WIDTH) - f1;
        bool fl0 = (lane >= P0B) &&
                   (V0 + fmaxf(e0 + mWp[lane], 0.f) * WIDTH >= theta);
        bool fl1 = (V1 + fmaxf(e1 + mWp[lane + 32], 0.f) * WIDTH >= theta);
        unsigned m0 = __ballot_sync(FULLM, fl0);
        unsigned m1 = __ballot_sync(FULLM, fl1);

        while (!done && m0) {
            int j = __ffs(m0) - 1;
            m0 &= m0 - 1;
            float cw0  = __shfl_sync(FULLM, e0, j);
            float cwt0 = __shfl_sync(FULLM, f0, j);
            int cnt = min(gather_range(j, j, sp, dT, bT, bI, lane), CAP);
            sort_shared(bT, bI, cnt, lane);
            if (eval_sorted(j, theta, cw0, cwt0, cnt, bT, bI, wT, lane, &res))
                done = true;
        }
        while (!done && m1) {
            int jl2 = __ffs(m1) - 1;
            m1 &= m1 - 1;
            float cw0  = __shfl_sync(FULLM, e1, jl2);
            float cwt0 = __shfl_sync(FULLM, f1, jl2);
            int j = jl2 + 32;
            int cnt = min(gather_range(j, j, sp, dT, bT, bI, lane), CAP);
            sort_shared(bT, bI, cnt, lane);
            if (eval_sorted(j, theta, cw0, cwt0, cnt, bT, bI, wT, lane, &res))
                done = true;
        }
        if (!done)
            res = (cwTot > 0.f) ? (theta + cwtTot) / cwTot : CUDART_INF_F;
    }

    if (lane == 0) out[(size_t)b * POSTN + post] = res;
}

// ---------------------------------------------------------------------------
extern "C" void kernel_launch(void* const* d_in, const int* in_sizes, int n_in,
                              void* d_out, int out_size)
{
    const float* spikes  = (const float*)d_in[0];  // [32, 1024]
    const float* weights = (const float*)d_in[1];  // [1024, 1024]
    const float* delays  = (const float*)d_in[2];  // [1024, 1024]
    const float* thr     = (const float*)d_in[3];  // [1024]
    float* out = (float*)d_out;                    // [32, 1024]

    dim3 tb(32, 8);
    dim3 tg(POSTN / 32, PRE / 32);
    transpose_kernel<<<tg, tb>>>(weights, delays);

    equaltime_kernel<<<(BATCH * POSTN) / NWARP, NTH>>>(spikes, thr, out);
}

// round 12
// speedup vs baseline: 2.6480x; 1.4392x over previous
#include <cuda_runtime.h>
#include <math_constants.h>

#define PRE    1024
#define POSTN  1024
#define BATCH  32
#define NBK    64
#define WIDTH  0.03125f
#define CAP    96
#define NTH    256
#define NWARP  8
#define FULLM  0xffffffffu
#define P0B    21          // pass-0 buckets [0,21) <=> t < 0.65625

// Transposed copies of delays/weights: [post][pre]
__device__ float g_dT[POSTN * PRE];
__device__ float g_wT[POSTN * PRE];

// ---------------------------------------------------------------------------
__global__ void transpose_kernel(const float* __restrict__ W,
                                 const float* __restrict__ D)
{
    __shared__ float tw[32][33];
    __shared__ float td[32][33];
    int x  = blockIdx.x * 32 + threadIdx.x;
    int y0 = blockIdx.y * 32;
#pragma unroll
    for (int j = 0; j < 32; j += 8) {
        tw[threadIdx.y + j][threadIdx.x] = W[(size_t)(y0 + threadIdx.y + j) * POSTN + x];
        td[threadIdx.y + j][threadIdx.x] = D[(size_t)(y0 + threadIdx.y + j) * POSTN + x];
    }
    __syncthreads();
    int xo  = blockIdx.y * 32 + threadIdx.x;
    int yo0 = blockIdx.x * 32;
#pragma unroll
    for (int j = 0; j < 32; j += 8) {
        g_wT[(size_t)(yo0 + threadIdx.y + j) * PRE + xo] = tw[threadIdx.x][threadIdx.y + j];
        g_dT[(size_t)(yo0 + threadIdx.y + j) * PRE + xo] = td[threadIdx.x][threadIdx.y + j];
    }
}

// ---------------------------------------------------------------------------
// Gather (t, w) of bucket-j events into shared. Loads only sp+dT vectors;
// w is scalar-loaded (L1-hot) ONLY for matched events. Deterministic order.
// ---------------------------------------------------------------------------
__device__ __forceinline__ int gather_single(
    int j,
    const float* __restrict__ sp, const float* __restrict__ dT,
    const float* __restrict__ wT,
    float* bT, float* bW, int lane)
{
    int cnt = 0;
#pragma unroll
    for (int r = 0; r < 8; r++) {
        int i0 = r * 128 + lane * 4;
        float4 s4 = *reinterpret_cast<const float4*>(sp + i0);
        float4 d4 = *reinterpret_cast<const float4*>(dT + i0);
        float tq[4] = { s4.x + d4.x, s4.y + d4.y, s4.z + d4.z, s4.w + d4.w };
#pragma unroll
        for (int q = 0; q < 4; q++) {
            int bb = (int)(tq[q] * 32.0f);     // t in [0,2) strictly
            bool in = (bb == j);
            unsigned m = __ballot_sync(FULLM, in);
            int pos = cnt + __popc(m & ((1u << lane) - 1));
            if (in && pos < CAP) { bT[pos] = tq[q]; bW[pos] = wT[i0 + q]; }
            cnt += __popc(m);
        }
    }
    __syncwarp();
    return min(cnt, CAP);
}

// ---------------------------------------------------------------------------
// Fused rank-prefix evaluation (NO sort). For each bucket event k, compute
// its exact prefix (cw0/cwt0 + sums over bucket events strictly before it in
// (t, position) order), test V(t_k) >= theta, and pick the earliest crosser
// by time (warp min-reduce). Drift crossing checked against bucket-end
// totals cwE/cwtE up to edge. Exact; tie order irrelevant (degenerate
// windows yield identical tmp).
// ---------------------------------------------------------------------------
__device__ __forceinline__ bool eval_fused(
    float theta, float cw0, float cwt0, float cwE, float cwtE, float edge,
    int cnt, const float* bT, const float* bW, int lane, float* outres)
{
    float bestT   = CUDART_INF_F;
    float bestTmp = CUDART_INF_F;
    for (int base = 0; base < cnt; base += 32) {
        int  k  = base + lane;
        bool on = (k < cnt);
        float tk = on ? bT[k] : 0.f;
        float sw = 0.f, swt = 0.f;
        for (int s = 0; s < cnt; s++) {
            float ts = bT[s], ws = bW[s];       // broadcast LDS
            bool before = (ts < tk) || (ts == tk && s < k);
            if (before) { sw += ws; swt = fmaf(ws, ts, swt); }
        }
        float CWp  = cw0  + sw;                 // prefix BEFORE event k
        float CWTp = cwt0 + swt;
        float V    = CWp * tk - CWTp;
        if (on && V >= theta && CWp > 0.f) {
            float tmp = (theta + CWTp) / CWp;
            if (tk < bestT) { bestT = tk; bestTmp = tmp; }
        }
    }
#pragma unroll
    for (int o = 16; o > 0; o >>= 1) {
        float ot   = __shfl_xor_sync(FULLM, bestT,   o);
        float otmp = __shfl_xor_sync(FULLM, bestTmp, o);
        if (ot < bestT) { bestT = ot; bestTmp = otmp; }
    }
    if (bestT < CUDART_INF_F) { *outres = bestTmp; return true; }
    if (cwE > 0.f && cwE * edge - cwtE >= theta) {   // drift before edge
        *outres = (theta + cwtE) / cwE;
        return true;
    }
    return false;
}

// ---------------------------------------------------------------------------
// One WARP per (batch, post) problem. No block-wide barriers.
// ---------------------------------------------------------------------------
__global__ __launch_bounds__(NTH, 4)
void equaltime_kernel(const float* __restrict__ spikes,
                      const float* __restrict__ thresholds,
                      float* __restrict__ out)
{
    __shared__ float sW[NWARP][NBK], sWT[NWARP][NBK], sWp[NWARP][NBK];
    __shared__ float sbT[NWARP][CAP], sbW[NWARP][CAP];

    const int lane = threadIdx.x & 31;
    const int wid  = threadIdx.x >> 5;
    const int pid  = blockIdx.x * NWARP + wid;
    const int post = pid >> 5;
    const int b    = pid & 31;

    const float theta = thresholds[post];
    const float* dT = g_dT + (size_t)post * PRE;
    const float* wT = g_wT + (size_t)post * PRE;
    const float* sp = spikes + (size_t)b * PRE;
    float* mW  = sW[wid];
    float* mWT = sWT[wid];
    float* mWp = sWp[wid];
    float* bT  = sbT[wid];
    float* bW  = sbW[wid];

    if (lane < P0B) { mW[lane] = 0.f; mWT[lane] = 0.f; mWp[lane] = 0.f; }
    __syncwarp();

    // ---- pass-0 sweep: bin sums for buckets [0,P0B) ----
#pragma unroll
    for (int r = 0; r < 8; r++) {
        int i0 = r * 128 + lane * 4;
        float4 s4 = *reinterpret_cast<const float4*>(sp + i0);
        float4 d4 = *reinterpret_cast<const float4*>(dT + i0);
        float4 w4 = *reinterpret_cast<const float4*>(wT + i0);
        float tq[4] = { s4.x + d4.x, s4.y + d4.y, s4.z + d4.z, s4.w + d4.w };
        float wq[4] = { w4.x, w4.y, w4.z, w4.w };
#pragma unroll
        for (int q = 0; q < 4; q++) {
            int bb = (int)(tq[q] * 32.0f);
            if (bb < P0B) {
                atomicAdd(&mW[bb],  wq[q]);
                atomicAdd(&mWT[bb], wq[q] * tq[q]);
                if (wq[q] > 0.f) atomicAdd(&mWp[bb], wq[q]);
            }
        }
    }
    __syncwarp();

    // ---- scan pass-0 bins, flag candidate buckets ----
    float wj  = (lane < P0B) ? mW[lane]  : 0.f;
    float wtj = (lane < P0B) ? mWT[lane] : 0.f;
    float a = wj, c = wtj;
#pragma unroll
    for (int o = 1; o < 32; o <<= 1) {
        float u = __shfl_up_sync(FULLM, a, o);
        float v = __shfl_up_sync(FULLM, c, o);
        if (lane >= o) { a += u; c += v; }
    }
    float e = a - wj, f = c - wtj;                 // exclusive prefixes
    float V = e * (lane * WIDTH) - f;
    float wp = (lane < P0B) ? mWp[lane] : 0.f;
    bool fl = (lane < P0B) && (V + fmaxf(e + wp, 0.f) * WIDTH >= theta);
    unsigned fm = __ballot_sync(FULLM, fl);

    float res  = CUDART_INF_F;
    bool  done = false;

    // ---- flagged buckets in time order, single-bucket fused eval ----
    while (!done && fm) {
        int j = __ffs(fm) - 1;
        fm &= fm - 1;
        int cnt = gather_single(j, sp, dT, wT, bT, bW, lane);
        float cw0  = __shfl_sync(FULLM, e, j);
        float cwt0 = __shfl_sync(FULLM, f, j);
        float cwE  = __shfl_sync(FULLM, a, j);     // inclusive = bucket end
        float cwtE = __shfl_sync(FULLM, c, j);
        if (eval_fused(theta, cw0, cwt0, cwE, cwtE,
                       (float)(j + 1) * WIDTH, cnt, bT, bW, lane, &res))
            done = true;
    }

    // ---- pass 1 (crossing at t >= 0.65625; ~8e-4 of problems, exact path) ----
    if (!done) {
        for (int jj = P0B + lane; jj < NBK; jj += 32) {
            mW[jj] = 0.f; mWT[jj] = 0.f; mWp[jj] = 0.f;
        }
        __syncwarp();
#pragma unroll
        for (int r = 0; r < 8; r++) {
            int i0 = r * 128 + lane * 4;
            float4 s4 = *reinterpret_cast<const float4*>(sp + i0);
            float4 d4 = *reinterpret_cast<const float4*>(dT + i0);
            float4 w4 = *reinterpret_cast<const float4*>(wT + i0);
            float tq[4] = { s4.x + d4.x, s4.y + d4.y, s4.z + d4.z, s4.w + d4.w };
            float wq[4] = { w4.x, w4.y, w4.z, w4.w };
#pragma unroll
            for (int q = 0; q < 4; q++) {
                int bb = (int)(tq[q] * 32.0f);
                if (bb >= P0B) {
                    atomicAdd(&mW[bb],  wq[q]);
                    atomicAdd(&mWT[bb], wq[q] * tq[q]);
                    if (wq[q] > 0.f) atomicAdd(&mWp[bb], wq[q]);
                }
            }
        }
        __syncwarp();

        float w0  = mW[lane],  w1  = mW[lane + 32];
        float wt0 = mWT[lane], wt1 = mWT[lane + 32];
        float a0 = w0, a1 = w1, b0 = wt0, b1 = wt1;
#pragma unroll
        for (int o = 1; o < 32; o <<= 1) {
            float u0 = __shfl_up_sync(FULLM, a0, o);
            float u1 = __shfl_up_sync(FULLM, a1, o);
            float v0 = __shfl_up_sync(FULLM, b0, o);
            float v1 = __shfl_up_sync(FULLM, b1, o);
            if (lane >= o) { a0 += u0; a1 += u1; b0 += v0; b1 += v1; }
        }
        float T0  = __shfl_sync(FULLM, a0, 31);
        float TW0 = __shfl_sync(FULLM, b0, 31);
        a1 += T0; b1 += TW0;
        float e0 = a0 - w0,  e1 = a1 - w1;
        float f0 = b0 - wt0, f1 = b1 - wt1;
        float cwTot  = __shfl_sync(FULLM, a1, 31);
        float cwtTot = __shfl_sync(FULLM, b1, 31);
        float V0 = e0 * (lane * WIDTH) - f0;
        float V1 = e1 * ((lane + 32) * WIDTH) - f1;
        bool fl0 = (lane >= P0B) &&
                   (V0 + fmaxf(e0 + mWp[lane], 0.f) * WIDTH >= theta);
        bool fl1 = (V1 + fmaxf(e1 + mWp[lane + 32], 0.f) * WIDTH >= theta);
        unsigned m0 = __ballot_sync(FULLM, fl0);
        unsigned m1 = __ballot_sync(FULLM, fl1);

        while (!done && m0) {
            int j = __ffs(m0) - 1;
            m0 &= m0 - 1;
            int cnt = gather_single(j, sp, dT, wT, bT, bW, lane);
            float cw0  = __shfl_sync(FULLM, e0, j);
            float cwt0 = __shfl_sync(FULLM, f0, j);
            float cwE  = __shfl_sync(FULLM, a0, j);
            float cwtE = __shfl_sync(FULLM, b0, j);
            if (eval_fused(theta, cw0, cwt0, cwE, cwtE,
                           (float)(j + 1) * WIDTH, cnt, bT, bW, lane, &res))
                done = true;
        }
        while (!done && m1) {
            int jl = __ffs(m1) - 1;
            m1 &= m1 - 1;
            int j = jl + 32;
            int cnt = gather_single(j, sp, dT, wT, bT, bW, lane);
            float cw0  = __shfl_sync(FULLM, e1, jl);
            float cwt0 = __shfl_sync(FULLM, f1, jl);
            float cwE  = __shfl_sync(FULLM, a1, jl);
            float cwtE = __shfl_sync(FULLM, b1, jl);
            if (eval_fused(theta, cw0, cwt0, cwE, cwtE,
                           (float)(j + 1) * WIDTH, cnt, bT, bW, lane, &res))
                done = true;
        }
        if (!done)
            res = (cwTot > 0.f) ? (theta + cwtTot) / cwTot : CUDART_INF_F;
    }

    if (lane == 0) out[(size_t)b * POSTN + post] = res;
}

// ---------------------------------------------------------------------------
extern "C" void kernel_launch(void* const* d_in, const int* in_sizes, int n_in,
                              void* d_out, int out_size)
{
    const float* spikes  = (const float*)d_in[0];  // [32, 1024]
    const float* weights = (const float*)d_in[1];  // [1024, 1024]
    const float* delays  = (const float*)d_in[2];  // [1024, 1024]
    const float* thr     = (const float*)d_in[3];  // [1024]
    float* out = (float*)d_out;                    // [32, 1024]

    dim3 tb(32, 8);
    dim3 tg(POSTN / 32, PRE / 32);
    transpose_kernel<<<tg, tb>>>(weights, delays);

    equaltime_kernel<<<(BATCH * POSTN) / NWARP, NTH>>>(spikes, thr, out);
}

// round 14
// speedup vs baseline: 2.7296x; 1.0308x over previous
#include <cuda_runtime.h>
#include <math_constants.h>

#define PRE    1024
#define POSTN  1024
#define BATCH  32
#define NBK    64
#define WIDTH  0.03125f
#define CAP    96
#define LCAP   320         // shared event-list capacity (mean 220, +7.7 sigma)
#define NTH    256
#define NWARP  8
#define FULLM  0xffffffffu
#define P0B    21          // pass-0 buckets [0,21) <=> t < 0.65625

// Transposed copies of delays/weights: [post][pre]
__device__ float g_dT[POSTN * PRE];
__device__ float g_wT[POSTN * PRE];

// ---------------------------------------------------------------------------
__global__ void transpose_kernel(const float* __restrict__ W,
                                 const float* __restrict__ D)
{
    __shared__ float tw[32][33];
    __shared__ float td[32][33];
    int x  = blockIdx.x * 32 + threadIdx.x;
    int y0 = blockIdx.y * 32;
#pragma unroll
    for (int j = 0; j < 32; j += 8) {
        tw[threadIdx.y + j][threadIdx.x] = W[(size_t)(y0 + threadIdx.y + j) * POSTN + x];
        td[threadIdx.y + j][threadIdx.x] = D[(size_t)(y0 + threadIdx.y + j) * POSTN + x];
    }
    __syncthreads();
    int xo  = blockIdx.y * 32 + threadIdx.x;
    int yo0 = blockIdx.x * 32;
#pragma unroll
    for (int j = 0; j < 32; j += 8) {
        g_wT[(size_t)(yo0 + threadIdx.y + j) * PRE + xo] = tw[threadIdx.x][threadIdx.y + j];
        g_dT[(size_t)(yo0 + threadIdx.y + j) * PRE + xo] = td[threadIdx.x][threadIdx.y + j];
    }
}

// ---------------------------------------------------------------------------
// Gather bucket-j events from the shared (t,w) list. Deterministic order.
// ---------------------------------------------------------------------------
__device__ __forceinline__ int gather_list(
    int j, const float2* lst, int listn,
    float* bT, float* bW, int lane)
{
    int cnt = 0;
    for (int base = 0; base < listn; base += 32) {
        int  p  = base + lane;
        bool on = (p < listn);
        float2 ev = on ? lst[p] : make_float2(1e9f, 0.f);
        bool in = on && ((int)(ev.x * 32.0f) == j);
        unsigned m = __ballot_sync(FULLM, in);
        int pos = cnt + __popc(m & ((1u << lane) - 1));
        if (in && pos < CAP) { bT[pos] = ev.x; bW[pos] = ev.y; }
        cnt += __popc(m);
    }
    __syncwarp();
    return min(cnt, CAP);
}

// ---------------------------------------------------------------------------
// Gather bucket-j events by full global re-sweep (fallback / pass-1 path).
// ---------------------------------------------------------------------------
__device__ __forceinline__ int gather_single(
    int j,
    const float* __restrict__ sp, const float* __restrict__ dT,
    const float* __restrict__ wT,
    float* bT, float* bW, int lane)
{
    int cnt = 0;
#pragma unroll
    for (int r = 0; r < 8; r++) {
        int i0 = r * 128 + lane * 4;
        float4 s4 = *reinterpret_cast<const float4*>(sp + i0);
        float4 d4 = *reinterpret_cast<const float4*>(dT + i0);
        float tq[4] = { s4.x + d4.x, s4.y + d4.y, s4.z + d4.z, s4.w + d4.w };
#pragma unroll
        for (int q = 0; q < 4; q++) {
            int bb = (int)(tq[q] * 32.0f);     // t in [0,2) strictly
            bool in = (bb == j);
            unsigned m = __ballot_sync(FULLM, in);
            int pos = cnt + __popc(m & ((1u << lane) - 1));
            if (in && pos < CAP) { bT[pos] = tq[q]; bW[pos] = wT[i0 + q]; }
            cnt += __popc(m);
        }
    }
    __syncwarp();
    return min(cnt, CAP);
}

// ---------------------------------------------------------------------------
// Fused rank-prefix evaluation (NO sort). For each bucket event k, compute
// its exact prefix (cw0/cwt0 + sums over bucket events strictly before it in
// (t, position) order), test V(t_k) >= theta, and pick the earliest crosser
// by time (warp min-reduce). Drift crossing checked against bucket-end
// totals cwE/cwtE up to edge. Exact; tie order irrelevant.
// ---------------------------------------------------------------------------
__device__ __forceinline__ bool eval_fused(
    float theta, float cw0, float cwt0, float cwE, float cwtE, float edge,
    int cnt, const float* bT, const float* bW, int lane, float* outres)
{
    float bestT   = CUDART_INF_F;
    float bestTmp = CUDART_INF_F;
    for (int base = 0; base < cnt; base += 32) {
        int  k  = base + lane;
        bool on = (k < cnt);
        float tk = on ? bT[k] : 0.f;
        float sw = 0.f, swt = 0.f;
        for (int s = 0; s < cnt; s++) {
            float ts = bT[s], ws = bW[s];       // broadcast LDS
            bool before = (ts < tk) || (ts == tk && s < k);
            if (before) { sw += ws; swt = fmaf(ws, ts, swt); }
        }
        float CWp  = cw0  + sw;                 // prefix BEFORE event k
        float CWTp = cwt0 + swt;
        float V    = CWp * tk - CWTp;
        if (on && V >= theta && CWp > 0.f) {
            float tmp = (theta + CWTp) / CWp;
            if (tk < bestT) { bestT = tk; bestTmp = tmp; }
        }
    }
#pragma unroll
    for (int o = 16; o > 0; o >>= 1) {
        float ot   = __shfl_xor_sync(FULLM, bestT,   o);
        float otmp = __shfl_xor_sync(FULLM, bestTmp, o);
        if (ot < bestT) { bestT = ot; bestTmp = otmp; }
    }
    if (bestT < CUDART_INF_F) { *outres = bestTmp; return true; }
    if (cwE > 0.f && cwE * edge - cwtE >= theta) {   // drift before edge
        *outres = (theta + cwtE) / cwE;
        return true;
    }
    return false;
}

// ---------------------------------------------------------------------------
// One WARP per (batch, post) problem. No block-wide barriers.
// ---------------------------------------------------------------------------
__global__ __launch_bounds__(NTH, 4)
void equaltime_kernel(const float* __restrict__ spikes,
                      const float* __restrict__ thresholds,
                      float* __restrict__ out)
{
    __shared__ float  sW[NWARP][NBK], sWT[NWARP][NBK], sWp[NWARP][NBK];
    __shared__ float  sbT[NWARP][CAP], sbW[NWARP][CAP];
    __shared__ float2 sLst[NWARP][LCAP];

    const int lane = threadIdx.x & 31;
    const int wid  = threadIdx.x >> 5;
    const int pid  = blockIdx.x * NWARP + wid;
    const int post = pid >> 5;
    const int b    = pid & 31;

    const float theta = thresholds[post];
    const float* dT = g_dT + (size_t)post * PRE;
    const float* wT = g_wT + (size_t)post * PRE;
    const float* sp = spikes + (size_t)b * PRE;
    float*  mW  = sW[wid];
    float*  mWT = sWT[wid];
    float*  mWp = sWp[wid];
    float*  bT  = sbT[wid];
    float*  bW  = sbW[wid];
    float2* lst = sLst[wid];

    if (lane < P0B) { mW[lane] = 0.f; mWT[lane] = 0.f; mWp[lane] = 0.f; }
    __syncwarp();

    // ---- pass-0 sweep: bin sums + compact (t,w) list for buckets [0,P0B) ----
    int listn = 0;
#pragma unroll
    for (int r = 0; r < 8; r++) {
        int i0 = r * 128 + lane * 4;
        float4 s4 = *reinterpret_cast<const float4*>(sp + i0);
        float4 d4 = *reinterpret_cast<const float4*>(dT + i0);
        float4 w4 = *reinterpret_cast<const float4*>(wT + i0);
        float tq[4] = { s4.x + d4.x, s4.y + d4.y, s4.z + d4.z, s4.w + d4.w };
        float wq[4] = { w4.x, w4.y, w4.z, w4.w };
#pragma unroll
        for (int q = 0; q < 4; q++) {
            int bb = (int)(tq[q] * 32.0f);
            bool in = (bb < P0B);
            if (in) {
                atomicAdd(&mW[bb],  wq[q]);
                atomicAdd(&mWT[bb], wq[q] * tq[q]);
                if (wq[q] > 0.f) atomicAdd(&mWp[bb], wq[q]);
            }
            unsigned m = __ballot_sync(FULLM, in);
            int pos = listn + __popc(m & ((1u << lane) - 1));
            if (in && pos < LCAP) lst[pos] = make_float2(tq[q], wq[q]);
            listn += __popc(m);
        }
    }
    __syncwarp();
    const bool list_ok = (listn <= LCAP);

    // ---- scan pass-0 bins, flag candidate buckets ----
    float wj  = (lane < P0B) ? mW[lane]  : 0.f;
    float wtj = (lane < P0B) ? mWT[lane] : 0.f;
    float a = wj, c = wtj;
#pragma unroll
    for (int o = 1; o < 32; o <<= 1) {
        float u = __shfl_up_sync(FULLM, a, o);
        float v = __shfl_up_sync(FULLM, c, o);
        if (lane >= o) { a += u; c += v; }
    }
    float e = a - wj, f = c - wtj;                 // exclusive prefixes
    float V = e * (lane * WIDTH) - f;
    float wp = (lane < P0B) ? mWp[lane] : 0.f;
    bool fl = (lane < P0B) && (V + fmaxf(e + wp, 0.f) * WIDTH >= theta);
    unsigned fm = __ballot_sync(FULLM, fl);

    float res  = CUDART_INF_F;
    bool  done = false;

    // ---- flagged buckets in time order, single-bucket fused eval ----
    while (!done && fm) {
        int j = __ffs(fm) - 1;
        fm &= fm - 1;
        int cnt = list_ok ? gather_list(j, lst, listn, bT, bW, lane)
                          : gather_single(j, sp, dT, wT, bT, bW, lane);
        float cw0  = __shfl_sync(FULLM, e, j);
        float cwt0 = __shfl_sync(FULLM, f, j);
        float cwE  = __shfl_sync(FULLM, a, j);     // inclusive = bucket end
        float cwtE = __shfl_sync(FULLM, c, j);
        if (eval_fused(theta, cw0, cwt0, cwE, cwtE,
                       (float)(j + 1) * WIDTH, cnt, bT, bW, lane, &res))
            done = true;
    }

    // ---- pass 1 (crossing at t >= 0.65625; ~8e-4 of problems, exact path) ----
    if (!done) {
        for (int jj = P0B + lane; jj < NBK; jj += 32) {
            mW[jj] = 0.f; mWT[jj] = 0.f; mWp[jj] = 0.f;
        }
        __syncwarp();
#pragma unroll
        for (int r = 0; r < 8; r++) {
            int i0 = r * 128 + lane * 4;
            float4 s4 = *reinterpret_cast<const float4*>(sp + i0);
            float4 d4 = *reinterpret_cast<const float4*>(dT + i0);
            float4 w4 = *reinterpret_cast<const float4*>(wT + i0);
            float tq[4] = { s4.x + d4.x, s4.y + d4.y, s4.z + d4.z, s4.w + d4.w };
            float wq[4] = { w4.x, w4.y, w4.z, w4.w };
#pragma unroll
            for (int q = 0; q < 4; q++) {
                int bb = (int)(tq[q] * 32.0f);
                if (bb >= P0B) {
                    atomicAdd(&mW[bb],  wq[q]);
                    atomicAdd(&mWT[bb], wq[q] * tq[q]);
                    if (wq[q] > 0.f) atomicAdd(&mWp[bb], wq[q]);
                }
            }
        }
        __syncwarp();

        float w0  = mW[lane],  w1  = mW[lane + 32];
        float wt0 = mWT[lane], wt1 = mWT[lane + 32];
        float a0 = w0, a1 = w1, b0 = wt0, b1 = wt1;
#pragma unroll
        for (int o = 1; o < 32; o <<= 1) {
            float u0 = __shfl_up_sync(FULLM, a0, o);
            float u1 = __shfl_up_sync(FULLM, a1, o);
            float v0 = __shfl_up_sync(FULLM, b0, o);
            float v1 = __shfl_up_sync(FULLM, b1, o);
            if (lane >= o) { a0 += u0; a1 += u1; b0 += v0; b1 += v1; }
        }
        float T0  = __shfl_sync(FULLM, a0, 31);
        float TW0 = __shfl_sync(FULLM, b0, 31);
        a1 += T0; b1 += TW0;
        float e0 = a0 - w0,  e1 = a1 - w1;
        float f0 = b0 - wt0, f1 = b1 - wt1;
        float cwTot  = __shfl_sync(FULLM, a1, 31);
        float cwtTot = __shfl_sync(FULLM, b1, 31);
        float V0 = e0 * (lane * WIDTH) - f0;
        float V1 = e1 * ((lane + 32) * WIDTH) - f1;
        bool fl0 = (lane >= P0B) &&
                   (V0 + fmaxf(e0 + mWp[lane], 0.f) * WIDTH >= theta);
        bool fl1 = (V1 + fmaxf(e1 + mWp[lane + 32], 0.f) * WIDTH >= theta);
        unsigned m0 = __ballot_sync(FULLM, fl0);
        unsigned m1 = __ballot_sync(FULLM, fl1);

        while (!done && m0) {
            int j = __ffs(m0) - 1;
            m0 &= m0 - 1;
            int cnt = gather_single(j, sp, dT, wT, bT, bW, lane);
            float cw0  = __shfl_sync(FULLM, e0, j);
            float cwt0 = __shfl_sync(FULLM, f0, j);
            float cwE  = __shfl_sync(FULLM, a0, j);
            float cwtE = __shfl_sync(FULLM, b0, j);
            if (eval_fused(theta, cw0, cwt0, cwE, cwtE,
                           (float)(j + 1) * WIDTH, cnt, bT, bW, lane, &res))
                done = true;
        }
        while (!done && m1) {
            int jl = __ffs(m1) - 1;
            m1 &= m1 - 1;
            int j = jl + 32;
            int cnt = gather_single(j, sp, dT, wT, bT, bW, lane);
            float cw0  = __shfl_sync(FULLM, e1, jl);
            float cwt0 = __shfl_sync(FULLM, f1, jl);
            float cwE  = __shfl_sync(FULLM, a1, jl);
            float cwtE = __shfl_sync(FULLM, b1, jl);
            if (eval_fused(theta, cw0, cwt0, cwE, cwtE,
                           (float)(j + 1) * WIDTH, cnt, bT, bW, lane, &res))
                done = true;
        }
        if (!done)
            res = (cwTot > 0.f) ? (theta + cwtTot) / cwTot : CUDART_INF_F;
    }

    if (lane == 0) out[(size_t)b * POSTN + post] = res;
}

// ---------------------------------------------------------------------------
extern "C" void kernel_launch(void* const* d_in, const int* in_sizes, int n_in,
                              void* d_out, int out_size)
{
    const float* spikes  = (const float*)d_in[0];  // [32, 1024]
    const float* weights = (const float*)d_in[1];  // [1024, 1024]
    const float* delays  = (const float*)d_in[2];  // [1024, 1024]
    const float* thr     = (const float*)d_in[3];  // [1024]
    float* out = (float*)d_out;                    // [32, 1024]

    dim3 tb(32, 8);
    dim3 tg(POSTN / 32, PRE / 32);
    transpose_kernel<<<tg, tb>>>(weights, delays);

    equaltime_kernel<<<(BATCH * POSTN) / NWARP, NTH>>>(spikes, thr, out);
}

// round 16
// speedup vs baseline: 2.9279x; 1.0727x over previous
#include <cuda_runtime.h>
#include <math_constants.h>

#define PRE    1024
#define POSTN  1024
#define BATCH  32
#define NBK    64
#define WIDTH  0.03125f
#define CAP    96
#define LCAP   320         // shared event-list capacity (mean 220, +7.7 sigma)
#define NTH    256
#define NWARP  8
#define FULLM  0xffffffffu
#define P0B    21          // pass-0 buckets [0,21) <=> t < 0.65625

// Transposed copies of delays/weights: [post][pre]
__device__ float g_dT[POSTN * PRE];
__device__ float g_wT[POSTN * PRE];

// ---------------------------------------------------------------------------
__global__ void transpose_kernel(const float* __restrict__ W,
                                 const float* __restrict__ D)
{
    __shared__ float tw[32][33];
    __shared__ float td[32][33];
    int x  = blockIdx.x * 32 + threadIdx.x;
    int y0 = blockIdx.y * 32;
#pragma unroll
    for (int j = 0; j < 32; j += 8) {
        tw[threadIdx.y + j][threadIdx.x] = W[(size_t)(y0 + threadIdx.y + j) * POSTN + x];
        td[threadIdx.y + j][threadIdx.x] = D[(size_t)(y0 + threadIdx.y + j) * POSTN + x];
    }
    __syncthreads();
    int xo  = blockIdx.y * 32 + threadIdx.x;
    int yo0 = blockIdx.x * 32;
#pragma unroll
    for (int j = 0; j < 32; j += 8) {
        g_wT[(size_t)(yo0 + threadIdx.y + j) * PRE + xo] = tw[threadIdx.x][threadIdx.y + j];
        g_dT[(size_t)(yo0 + threadIdx.y + j) * PRE + xo] = td[threadIdx.x][threadIdx.y + j];
    }
}

// ---------------------------------------------------------------------------
// Gather bucket-j events from the shared (t,w) list. Deterministic order.
// ---------------------------------------------------------------------------
__device__ __forceinline__ int gather_list(
    int j, const float2* lst, int listn,
    float* bT, float* bW, int lane, unsigned lmask)
{
    int cnt = 0;
    for (int base = 0; base < listn; base += 32) {
        int  p  = base + lane;
        bool on = (p < listn);
        float2 ev = on ? lst[p] : make_float2(1e9f, 0.f);
        bool in = on && ((int)(ev.x * 32.0f) == j);
        unsigned m = __ballot_sync(FULLM, in);
        int pos = cnt + __popc(m & lmask);
        if (in && pos < CAP) { bT[pos] = ev.x; bW[pos] = ev.y; }
        cnt += __popc(m);
    }
    __syncwarp();
    return min(cnt, CAP);
}

// ---------------------------------------------------------------------------
// Gather bucket-j events by full global re-sweep (fallback / pass-1 path).
// ---------------------------------------------------------------------------
__device__ __forceinline__ int gather_single(
    int j,
    const float* __restrict__ sp, const float* __restrict__ dT,
    const float* __restrict__ wT,
    float* bT, float* bW, int lane, unsigned lmask)
{
    int cnt = 0;
#pragma unroll
    for (int r = 0; r < 8; r++) {
        int i0 = r * 128 + lane * 4;
        float4 s4 = *reinterpret_cast<const float4*>(sp + i0);
        float4 d4 = *reinterpret_cast<const float4*>(dT + i0);
        float tq[4] = { s4.x + d4.x, s4.y + d4.y, s4.z + d4.z, s4.w + d4.w };
#pragma unroll
        for (int q = 0; q < 4; q++) {
            int bb = (int)(tq[q] * 32.0f);     // t in [0,2) strictly
            bool in = (bb == j);
            unsigned m = __ballot_sync(FULLM, in);
            int pos = cnt + __popc(m & lmask);
            if (in && pos < CAP) { bT[pos] = tq[q]; bW[pos] = wT[i0 + q]; }
            cnt += __popc(m);
        }
    }
    __syncwarp();
    return min(cnt, CAP);
}

// ---------------------------------------------------------------------------
// Fused rank-prefix evaluation (NO sort). Exact; tie order irrelevant.
// ---------------------------------------------------------------------------
__device__ __forceinline__ bool eval_fused(
    float theta, float cw0, float cwt0, float cwE, float cwtE, float edge,
    int cnt, const float* bT, const float* bW, int lane, float* outres)
{
    float bestT   = CUDART_INF_F;
    float bestTmp = CUDART_INF_F;
    for (int base = 0; base < cnt; base += 32) {
        int  k  = base + lane;
        bool on = (k < cnt);
        float tk = on ? bT[k] : 0.f;
        float sw = 0.f, swt = 0.f;
        for (int s = 0; s < cnt; s++) {
            float ts = bT[s], ws = bW[s];       // broadcast LDS
            bool before = (ts < tk) || (ts == tk && s < k);
            if (before) { sw += ws; swt = fmaf(ws, ts, swt); }
        }
        float CWp  = cw0  + sw;                 // prefix BEFORE event k
        float CWTp = cwt0 + swt;
        float V    = CWp * tk - CWTp;
        if (on && V >= theta && CWp > 0.f) {
            float tmp = (theta + CWTp) / CWp;
            if (tk < bestT) { bestT = tk; bestTmp = tmp; }
        }
    }
#pragma unroll
    for (int o = 16; o > 0; o >>= 1) {
        float ot   = __shfl_xor_sync(FULLM, bestT,   o);
        float otmp = __shfl_xor_sync(FULLM, bestTmp, o);
        if (ot < bestT) { bestT = ot; bestTmp = otmp; }
    }
    if (bestT < CUDART_INF_F) { *outres = bestTmp; return true; }
    if (cwE > 0.f && cwE * edge - cwtE >= theta) {   // drift before edge
        *outres = (theta + cwtE) / cwE;
        return true;
    }
    return false;
}

// ---------------------------------------------------------------------------
// COLD PATH (~0.08% of warps): crossing at t >= 0.65625. Bins buckets
// [P0B,64), full 64-bucket scan (pass-0 bins in mW/mWT/mWp intact), candidate
// loop, final open-window fallback. __noinline__ keeps its registers out of
// the hot path's allocation.
// ---------------------------------------------------------------------------
__device__ __noinline__ float pass1_cold(
    float theta,
    const float* __restrict__ sp, const float* __restrict__ dT,
    const float* __restrict__ wT,
    float* mW, float* mWT, float* mWp,
    float* bT, float* bW, int lane, unsigned lmask)
{
    for (int jj = P0B + lane; jj < NBK; jj += 32) {
        mW[jj] = 0.f; mWT[jj] = 0.f; mWp[jj] = 0.f;
    }
    __syncwarp();
#pragma unroll
    for (int r = 0; r < 8; r++) {
        int i0 = r * 128 + lane * 4;
        float4 s4 = *reinterpret_cast<const float4*>(sp + i0);
        float4 d4 = *reinterpret_cast<const float4*>(dT + i0);
        float4 w4 = *reinterpret_cast<const float4*>(wT + i0);
        float tq[4] = { s4.x + d4.x, s4.y + d4.y, s4.z + d4.z, s4.w + d4.w };
        float wq[4] = { w4.x, w4.y, w4.z, w4.w };
#pragma unroll
        for (int q = 0; q < 4; q++) {
            int bb = (int)(tq[q] * 32.0f);
            if (bb >= P0B) {
                atomicAdd(&mW[bb],  wq[q]);
                atomicAdd(&mWT[bb], wq[q] * tq[q]);
                if (wq[q] > 0.f) atomicAdd(&mWp[bb], wq[q]);
            }
        }
    }
    __syncwarp();

    float w0  = mW[lane],  w1  = mW[lane + 32];
    float wt0 = mWT[lane], wt1 = mWT[lane + 32];
    float a0 = w0, a1 = w1, b0 = wt0, b1 = wt1;
#pragma unroll
    for (int o = 1; o < 32; o <<= 1) {
        float u0 = __shfl_up_sync(FULLM, a0, o);
        float u1 = __shfl_up_sync(FULLM, a1, o);
        float v0 = __shfl_up_sync(FULLM, b0, o);
        float v1 = __shfl_up_sync(FULLM, b1, o);
        if (lane >= o) { a0 += u0; a1 += u1; b0 += v0; b1 += v1; }
    }
    float T0  = __shfl_sync(FULLM, a0, 31);
    float TW0 = __shfl_sync(FULLM, b0, 31);
    a1 += T0; b1 += TW0;
    float e0 = a0 - w0,  e1 = a1 - w1;
    float f0 = b0 - wt0, f1 = b1 - wt1;
    float cwTot  = __shfl_sync(FULLM, a1, 31);
    float cwtTot = __shfl_sync(FULLM, b1, 31);
    float V0 = e0 * (lane * WIDTH) - f0;
    float V1 = e1 * ((lane + 32) * WIDTH) - f1;
    bool fl0 = (lane >= P0B) &&
               (V0 + fmaxf(e0 + mWp[lane], 0.f) * WIDTH >= theta);
    bool fl1 = (V1 + fmaxf(e1 + mWp[lane + 32], 0.f) * WIDTH >= theta);
    unsigned m0 = __ballot_sync(FULLM, fl0);
    unsigned m1 = __ballot_sync(FULLM, fl1);

    float res = CUDART_INF_F;
    while (m0) {
        int j = __ffs(m0) - 1;
        m0 &= m0 - 1;
        int cnt = gather_single(j, sp, dT, wT, bT, bW, lane, lmask);
        float cw0  = __shfl_sync(FULLM, e0, j);
        float cwt0 = __shfl_sync(FULLM, f0, j);
        float cwE  = __shfl_sync(FULLM, a0, j);
        float cwtE = __shfl_sync(FULLM, b0, j);
        if (eval_fused(theta, cw0, cwt0, cwE, cwtE,
                       (float)(j + 1) * WIDTH, cnt, bT, bW, lane, &res))
            return res;
    }
    while (m1) {
        int jl = __ffs(m1) - 1;
        m1 &= m1 - 1;
        int j = jl + 32;
        int cnt = gather_single(j, sp, dT, wT, bT, bW, lane, lmask);
        float cw0  = __shfl_sync(FULLM, e1, jl);
        float cwt0 = __shfl_sync(FULLM, f1, jl);
        float cwE  = __shfl_sync(FULLM, a1, jl);
        float cwtE = __shfl_sync(FULLM, b1, jl);
        if (eval_fused(theta, cw0, cwt0, cwE, cwtE,
                       (float)(j + 1) * WIDTH, cnt, bT, bW, lane, &res))
            return res;
    }
    return (cwTot > 0.f) ? (theta + cwtTot) / cwTot : CUDART_INF_F;
}

// ---------------------------------------------------------------------------
// One WARP per (batch, post) problem. No block-wide barriers.
// ---------------------------------------------------------------------------
__global__ __launch_bounds__(NTH, 5)
void equaltime_kernel(const float* __restrict__ spikes,
                      const float* __restrict__ thresholds,
                      float* __restrict__ out)
{
    __shared__ float  sW[NWARP][NBK], sWT[NWARP][NBK], sWp[NWARP][NBK];
    __shared__ float  sbT[NWARP][CAP], sbW[NWARP][CAP];
    __shared__ float2 sLst[NWARP][LCAP];

    const int lane = threadIdx.x & 31;
    const int wid  = threadIdx.x >> 5;
    const unsigned lmask = (1u << lane) - 1;
    const int pid  = blockIdx.x * NWARP + wid;
    const int post = pid >> 5;
    const int b    = pid & 31;

    const float theta = thresholds[post];
    const float* dT = g_dT + (size_t)post * PRE;
    const float* wT = g_wT + (size_t)post * PRE;
    const float* sp = spikes + (size_t)b * PRE;
    float*  mW  = sW[wid];
    float*  mWT = sWT[wid];
    float*  mWp = sWp[wid];
    float*  bT  = sbT[wid];
    float*  bW  = sbW[wid];
    float2* lst = sLst[wid];

    if (lane < P0B) { mW[lane] = 0.f; mWT[lane] = 0.f; mWp[lane] = 0.f; }
    __syncwarp();

    // ---- pass-0 sweep: bin sums + compact (t,w) list for buckets [0,P0B) ----
    int listn = 0;
#pragma unroll
    for (int r = 0; r < 8; r++) {
        int i0 = r * 128 + lane * 4;
        float4 s4 = *reinterpret_cast<const float4*>(sp + i0);
        float4 d4 = *reinterpret_cast<const float4*>(dT + i0);
        float4 w4 = *reinterpret_cast<const float4*>(wT + i0);
        float tq[4] = { s4.x + d4.x, s4.y + d4.y, s4.z + d4.z, s4.w + d4.w };
        float wq[4] = { w4.x, w4.y, w4.z, w4.w };
#pragma unroll
        for (int q = 0; q < 4; q++) {
            int bb = (int)(tq[q] * 32.0f);
            bool in = (bb < P0B);
            if (in) {
                atomicAdd(&mW[bb],  wq[q]);
                atomicAdd(&mWT[bb], wq[q] * tq[q]);
                if (wq[q] > 0.f) atomicAdd(&mWp[bb], wq[q]);
            }
            unsigned m = __ballot_sync(FULLM, in);
            int pos = listn + __popc(m & lmask);
            if (in && pos < LCAP) lst[pos] = make_float2(tq[q], wq[q]);
            listn += __popc(m);
        }
    }
    __syncwarp();
    const bool list_ok = (listn <= LCAP);

    // ---- scan pass-0 bins, flag candidate buckets ----
    float wj  = (lane < P0B) ? mW[lane]  : 0.f;
    float wtj = (lane < P0B) ? mWT[lane] : 0.f;
    float a = wj, c = wtj;
#pragma unroll
    for (int o = 1; o < 32; o <<= 1) {
        float u = __shfl_up_sync(FULLM, a, o);
        float v = __shfl_up_sync(FULLM, c, o);
        if (lane >= o) { a += u; c += v; }
    }
    float e = a - wj, f = c - wtj;                 // exclusive prefixes
    float V = e * (lane * WIDTH) - f;
    float wp = (lane < P0B) ? mWp[lane] : 0.f;
    bool fl = (lane < P0B) && (V + fmaxf(e + wp, 0.f) * WIDTH >= theta);
    unsigned fm = __ballot_sync(FULLM, fl);

    float res  = CUDART_INF_F;
    bool  done = false;

    // ---- flagged buckets in time order, single-bucket fused eval ----
    while (!done && fm) {
        int j = __ffs(fm) - 1;
        fm &= fm - 1;
        int cnt = list_ok ? gather_list(j, lst, listn, bT, bW, lane, lmask)
                          : gather_single(j, sp, dT, wT, bT, bW, lane, lmask);
        float cw0  = __shfl_sync(FULLM, e, j);
        float cwt0 = __shfl_sync(FULLM, f, j);
        float cwE  = __shfl_sync(FULLM, a, j);     // inclusive = bucket end
        float cwtE = __shfl_sync(FULLM, c, j);
        if (eval_fused(theta, cw0, cwt0, cwE, cwtE,
                       (float)(j + 1) * WIDTH, cnt, bT, bW, lane, &res))
            done = true;
    }

    // ---- pass 1: cold, exact fallback ----
    if (!done)
        res = pass1_cold(theta, sp, dT, wT, mW, mWT, mWp, bT, bW, lane, lmask);

    if (lane == 0) out[(size_t)b * POSTN + post] = res;
}

// ---------------------------------------------------------------------------
extern "C" void kernel_launch(void* const* d_in, const int* in_sizes, int n_in,
                              void* d_out, int out_size)
{
    const float* spikes  = (const float*)d_in[0];  // [32, 1024]
    const float* weights = (const float*)d_in[1];  // [1024, 1024]
    const float* delays  = (const float*)d_in[2];  // [1024, 1024]
    const float* thr     = (const float*)d_in[3];  // [1024]
    float* out = (float*)d_out;                    // [32, 1024]

    dim3 tb(32, 8);
    dim3 tg(POSTN / 32, PRE / 32);
    transpose_kernel<<<tg, tb>>>(weights, delays);

    equaltime_kernel<<<(BATCH * POSTN) / NWARP, NTH>>>(spikes, thr, out);
}